// round 15
// baseline (speedup 1.0000x reference)
#include <cuda_runtime.h>
#include <float.h>

#define BT     (16 * 512)   // 8192 pairs
#define IDIM   80
#define HDIM   512
#define NSHIFT 159
#define PAD    79
#define SKP    248

typedef unsigned long long ull;

// Scratch: x_attn stored as fp16 bits (allocation-free rule: __device__ global)
__device__ unsigned short g_xattn_h[BT * IDIM];

__device__ __forceinline__ float warpReduceSum(float v) {
#pragma unroll
    for (int o = 16; o; o >>= 1) v += __shfl_xor_sync(0xffffffffu, v, o);
    return v;
}
__device__ __forceinline__ float warpReduceMax(float v) {
#pragma unroll
    for (int o = 16; o; o >>= 1) v = fmaxf(v, __shfl_xor_sync(0xffffffffu, v, o));
    return v;
}

#define FMA2(D, A, B) \
    asm("fma.rn.f32x2 %0, %1, %2, %0;" : "+l"(D) : "l"(A), "l"(B))
#define PACK2(D, LO, HI) \
    asm("mov.b64 %0, {%1, %2};" : "=l"(D) : "f"(LO), "f"(HI))

__device__ __forceinline__ float ull_sum2(ull v) {
    float lo, hi;
    asm("mov.b64 {%0, %1}, %2;" : "=f"(lo), "=f"(hi) : "l"(v));
    return lo + hi;
}

// ---------------------------------------------------------------------------
// Kernel 1: warp-per-pair. R15: packed f32x2 dot loop over i-PAIRS with
// STABLE register pairing (advance-by-2 => Q0'..Q2' are renames; only 2 new
// pairs built per iter from 2 conflict-free scalar LDS). Shared-core
// all-positive norm decomposition (R6-validated). Output fp16 (R14).
// ---------------------------------------------------------------------------
#define PAIRS_PER_BLK 8
__global__ __launch_bounds__(256) void attn_kernel(
    const float* __restrict__ x, const float* __restrict__ y,
    unsigned short* __restrict__ xattn_h)
{
    const int warp = threadIdx.x >> 5;
    const int lane = threadIdx.x & 31;
    const int p    = blockIdx.x * PAIRS_PER_BLK + warp;

    __shared__ __align__(16) float kp[PAIRS_PER_BLK][SKP];
    __shared__ __align__(16) float ys[PAIRS_PER_BLK][IDIM];
    float* kpw = kp[warp];
    float* ysw = ys[warp];

    for (int i = lane; i < SKP; i += 32) kpw[i] = 0.0f;
    __syncwarp();

    const float* xp = x + (size_t)p * IDIM;
    const float* yp = y + (size_t)p * IDIM;
    float yn2 = 0.0f;
    for (int i = lane; i < IDIM; i += 32) {
        kpw[PAD + i] = xp[i];
        float v = yp[i];
        ysw[i] = v;
        yn2 = fmaf(v, v, yn2);
    }
    yn2 = warpReduceSum(yn2);
    __syncwarp();

    const int base = lane * 5;
    const ull* ys64 = reinterpret_cast<const ull*>(ysw);

    // initial frame: v_j = kp[base+j], j=0..5; pairs Q_j = (v_j, v_{j+1})
    float v0 = kpw[base + 0], v1 = kpw[base + 1], v2 = kpw[base + 2],
          v3 = kpw[base + 3], v4 = kpw[base + 4], v5 = kpw[base + 5];
    ull Q0, Q1, Q2, Q3, Q4;
    PACK2(Q0, v0, v1);
    PACK2(Q1, v1, v2);
    PACK2(Q2, v2, v3);
    PACK2(Q3, v3, v4);
    PACK2(Q4, v4, v5);
    float t5 = v5;

    ull D0 = 0, D1 = 0, D2 = 0, D3 = 0, D4 = 0, C = 0;
#pragma unroll
    for (int m = 0; m < 40; ++m) {
        ull Y = ys64[m];
        FMA2(D0, Q0, Y);
        FMA2(D1, Q1, Y);
        FMA2(D2, Q2, Y);
        FMA2(D3, Q3, Y);
        FMA2(D4, Q4, Y);
        if (m < 38) FMA2(C, Q4, Q4);   // core: kp[base+4 .. base+79]^2
        if (m < 39) {
            float a = kpw[base + 2 * m + 6];
            float b = kpw[base + 2 * m + 7];
            Q0 = Q2; Q1 = Q3; Q2 = Q4;
            PACK2(Q3, t5, a);
            PACK2(Q4, a, b);
            t5 = b;
        }
    }

    float dotv[5];
    dotv[0] = ull_sum2(D0);
    dotv[1] = ull_sum2(D1);
    dotv[2] = ull_sum2(D2);
    dotv[3] = ull_sum2(D3);
    dotv[4] = ull_sum2(D4);
    const float core = ull_sum2(C);

    // head/tail fixups (scalar, all-positive; R6-validated)
    const float i0 = kpw[base + 0], i1 = kpw[base + 1],
                i2 = kpw[base + 2], i3 = kpw[base + 3];
    const float t0 = kpw[base + 80], t1 = kpw[base + 81],
                t2 = kpw[base + 82], t3 = kpw[base + 83];
    const float H3 = i3 * i3;
    const float H2 = fmaf(i2, i2, H3);
    const float H1 = fmaf(i1, i1, H2);
    const float H0 = fmaf(i0, i0, H1);
    const float T1 = t0 * t0;
    const float T2 = fmaf(t1, t1, T1);
    const float T3 = fmaf(t2, t2, T2);
    const float T4 = fmaf(t3, t3, T3);

    float n2v[5];
    n2v[0] = H0 + core;
    n2v[1] = (H1 + core) + T1;
    n2v[2] = (H2 + core) + T2;
    n2v[3] = (H3 + core) + T3;
    n2v[4] = core + T4;

    const float yn = sqrtf(yn2);
    float best = -FLT_MAX;
    int   bidx = 0;
#pragma unroll
    for (int j = 0; j < 5; ++j) {
        int s = base + j;
        if (s < NSHIFT) {
            float den = sqrtf(n2v[j]) * yn;
            float sim = (den > 0.0f) ? (dotv[j] / den) : 0.0f;
            if (sim > best) { best = sim; bidx = s; }
        }
    }
#pragma unroll
    for (int o = 16; o; o >>= 1) {
        float ov = __shfl_xor_sync(0xffffffffu, best, o);
        int   oi = __shfl_xor_sync(0xffffffffu, bidx, o);
        if (ov > best || (ov == best && oi < bidx)) { best = ov; bidx = oi; }
    }
    const int bs = bidx;

    float xa[3], sc[3];
    float m2 = -FLT_MAX;
#pragma unroll
    for (int t = 0; t < 3; ++t) {
        int i = lane + t * 32;
        if (i < IDIM) {
            xa[t] = kpw[bs + i];
            sc[t] = xa[t] * ysw[i];
            m2 = fmaxf(m2, sc[t]);
        }
    }
    m2 = warpReduceMax(m2);
    float sum = 0.0f, e[3];
#pragma unroll
    for (int t = 0; t < 3; ++t) {
        int i = lane + t * 32;
        if (i < IDIM) { e[t] = expf((sc[t] - m2) * 0.1f); sum += e[t]; }
    }
    sum = warpReduceSum(sum);
    const float inv = 1.0f / sum;
#pragma unroll
    for (int t = 0; t < 3; ++t) {
        int i = lane + t * 32;
        if (i < IDIM) {
            float v = xa[t] * (e[t] * inv);
            unsigned short h;
            asm("cvt.rn.f16.f32 %0, %1;" : "=h"(h) : "f"(v));
            xattn_h[(size_t)p * IDIM + i] = h;
        }
    }
}

// ---------------------------------------------------------------------------
// Kernel 2 (UNCHANGED from R14 — validated): fp16 mma.m16n8k16 with
// ldmatrix fragment loads; fp16 A tile copied raw. Block 128x128.
// ---------------------------------------------------------------------------
#define SP2 44   // uint stride per row

__device__ __forceinline__ unsigned f16pack(float v0, float v1) {
    unsigned r;
    asm("cvt.rn.f16x2.f32 %0, %1, %2;" : "=r"(r) : "f"(v1), "f"(v0));
    return r;
}

__device__ __forceinline__ void mma_f16(float d[4],
                                        unsigned a0, unsigned a1,
                                        unsigned a2, unsigned a3,
                                        unsigned b0, unsigned b1) {
    asm("mma.sync.aligned.m16n8k16.row.col.f32.f16.f16.f32 "
        "{%0,%1,%2,%3}, {%4,%5,%6,%7}, {%8,%9}, {%0,%1,%2,%3};"
        : "+f"(d[0]), "+f"(d[1]), "+f"(d[2]), "+f"(d[3])
        : "r"(a0), "r"(a1), "r"(a2), "r"(a3), "r"(b0), "r"(b1));
}

__device__ __forceinline__ void ldsm_x4(unsigned& r0, unsigned& r1,
                                        unsigned& r2, unsigned& r3,
                                        unsigned addr) {
    asm volatile("ldmatrix.sync.aligned.m8n8.x4.shared.b16 {%0,%1,%2,%3}, [%4];"
                 : "=r"(r0), "=r"(r1), "=r"(r2), "=r"(r3) : "r"(addr));
}

__global__ __launch_bounds__(256, 2) void gemm_kernel(
    const unsigned short* __restrict__ Ah, const float* __restrict__ W,
    const float* __restrict__ bias, float* __restrict__ out)
{
    extern __shared__ unsigned smem_u[];
    unsigned* As = smem_u;
    unsigned* Bs = smem_u + 128 * SP2;

    const int bn  = blockIdx.x * 128;
    const int bm  = blockIdx.y * 128;
    const int tid = threadIdx.x;
    const int warp = tid >> 5, lane = tid & 31;
    const int wm = warp >> 2;
    const int wn = warp & 3;
    const int g  = lane >> 2;
    const int t  = lane & 3;

#pragma unroll
    for (int it = 0; it < 5; ++it) {
        int idx = tid + it * 256;
        int row = idx / 10;
        int c4  = (idx % 10) * 4;
        uint4 a = *reinterpret_cast<const uint4*>(
            Ah + (size_t)(bm + row) * IDIM + c4 * 2);
        *reinterpret_cast<uint4*>(&As[row * SP2 + c4]) = a;
    }
#pragma unroll
    for (int it = 0; it < 10; ++it) {
        int idx = tid + it * 256;
        int row = idx / 20;
        int k4  = (idx % 20) * 4;
        int c   = k4 >> 1;
        float4 b = *reinterpret_cast<const float4*>(W + (size_t)(bn + row) * IDIM + k4);
        *reinterpret_cast<uint2*>(&Bs[row * SP2 + c]) =
            make_uint2(f16pack(b.x, b.y), f16pack(b.z, b.w));
    }
    __syncthreads();

    unsigned a_addr[4];
#pragma unroll
    for (int mt = 0; mt < 4; ++mt) {
        int row = wm * 64 + mt * 16 + (lane & 7) + ((lane >> 3) & 1) * 8;
        int uoff = row * SP2 + (lane >> 4) * 4;
        a_addr[mt] = (unsigned)__cvta_generic_to_shared(As + uoff);
    }
    unsigned b_addr[2];
#pragma unroll
    for (int j = 0; j < 2; ++j) {
        int row = wn * 32 + j * 16 + (lane & 7) + ((lane >> 4) & 1) * 8;
        int uoff = row * SP2 + ((lane >> 3) & 1) * 4;
        b_addr[j] = (unsigned)__cvta_generic_to_shared(Bs + uoff);
    }

    float d[4][4][4];
#pragma unroll
    for (int mt = 0; mt < 4; ++mt)
#pragma unroll
        for (int nt = 0; nt < 4; ++nt)
#pragma unroll
            for (int r = 0; r < 4; ++r) d[mt][nt][r] = 0.0f;

#pragma unroll
    for (int kc = 0; kc < 5; ++kc) {
        const unsigned koff = kc * 32;

        unsigned b0[4], b1[4];
        ldsm_x4(b0[0], b1[0], b0[1], b1[1], b_addr[0] + koff);
        ldsm_x4(b0[2], b1[2], b0[3], b1[3], b_addr[1] + koff);

#pragma unroll
        for (int mt = 0; mt < 4; ++mt) {
            unsigned a0, a1, a2, a3;
            ldsm_x4(a0, a1, a2, a3, a_addr[mt] + koff);
#pragma unroll
            for (int nt = 0; nt < 4; ++nt)
                mma_f16(d[mt][nt], a0, a1, a2, a3, b0[nt], b1[nt]);
        }
    }

#pragma unroll
    for (int mt = 0; mt < 4; ++mt) {
#pragma unroll
        for (int nt = 0; nt < 4; ++nt) {
            int row = bm + wm * 64 + mt * 16 + g;
            int col = bn + wn * 32 + nt * 8 + 2 * t;
            float b0 = __ldg(bias + col), b1 = __ldg(bias + col + 1);
            float2 o0 = make_float2(d[mt][nt][0] + b0, d[mt][nt][1] + b1);
            float2 o1 = make_float2(d[mt][nt][2] + b0, d[mt][nt][3] + b1);
            *reinterpret_cast<float2*>(out + (size_t)row * HDIM + col) = o0;
            *reinterpret_cast<float2*>(out + (size_t)(row + 8) * HDIM + col) = o1;
        }
    }
}

extern "C" void kernel_launch(void* const* d_in, const int* in_sizes, int n_in,
                              void* d_out, int out_size)
{
    const float* x    = (const float*)d_in[0];
    const float* y    = (const float*)d_in[1];
    const float* fc1w = (const float*)d_in[2];
    const float* fc1b = (const float*)d_in[3];
    float* out = (float*)d_out;

    unsigned short* xattn_h = nullptr;
    cudaGetSymbolAddress((void**)&xattn_h, g_xattn_h);

    attn_kernel<<<BT / PAIRS_PER_BLK, 256>>>(x, y, xattn_h);

    const int smem_bytes = 2 * 128 * SP2 * (int)sizeof(unsigned);  // 45056
    cudaFuncSetAttribute(gemm_kernel,
                         cudaFuncAttributeMaxDynamicSharedMemorySize, smem_bytes);
    gemm_kernel<<<dim3(HDIM / 128, BT / 128), 256, smem_bytes>>>(
        xattn_h, fc1w, fc1b, out);
}

// round 16
// speedup vs baseline: 1.0870x; 1.0870x over previous
#include <cuda_runtime.h>
#include <float.h>

#define BT     (16 * 512)   // 8192 pairs
#define IDIM   80
#define HDIM   512
#define NSHIFT 159
#define PAD    79
#define SKP    248

// Scratch: x_attn stored as fp16 bits (allocation-free rule: __device__ global)
__device__ unsigned short g_xattn_h[BT * IDIM];

__device__ __forceinline__ float warpReduceSum(float v) {
#pragma unroll
    for (int o = 16; o; o >>= 1) v += __shfl_xor_sync(0xffffffffu, v, o);
    return v;
}
__device__ __forceinline__ float warpReduceMax(float v) {
#pragma unroll
    for (int o = 16; o; o >>= 1) v = fmaxf(v, __shfl_xor_sync(0xffffffffu, v, o));
    return v;
}

// ---------------------------------------------------------------------------
// Kernel 1: warp-per-2-pairs (ILP-2). Per-pair math is the R14-validated
// scalar sequence, duplicated and interleaved in one loop body.
// 512 CTAs x 256 thr; 16 pairs/CTA -> single wave (4096 warps).
// ---------------------------------------------------------------------------
#define PAIRS_PER_BLK 16
__global__ __launch_bounds__(256, 4) void attn_kernel(
    const float* __restrict__ x, const float* __restrict__ y,
    unsigned short* __restrict__ xattn_h)
{
    const int warp = threadIdx.x >> 5;
    const int lane = threadIdx.x & 31;
    const int pA   = blockIdx.x * PAIRS_PER_BLK + 2 * warp;
    const int pB   = pA + 1;

    __shared__ float kp[PAIRS_PER_BLK][SKP];
    __shared__ float ys[PAIRS_PER_BLK][IDIM];
    float* kpA = kp[2 * warp];
    float* kpB = kp[2 * warp + 1];
    float* ysA = ys[2 * warp];
    float* ysB = ys[2 * warp + 1];

    for (int i = lane; i < SKP; i += 32) { kpA[i] = 0.0f; kpB[i] = 0.0f; }
    __syncwarp();

    const float* xpA = x + (size_t)pA * IDIM;
    const float* ypA = y + (size_t)pA * IDIM;
    const float* xpB = x + (size_t)pB * IDIM;
    const float* ypB = y + (size_t)pB * IDIM;
    float ynA = 0.0f, ynB = 0.0f;
    for (int i = lane; i < IDIM; i += 32) {
        kpA[PAD + i] = xpA[i];
        kpB[PAD + i] = xpB[i];
        float va = ypA[i], vb = ypB[i];
        ysA[i] = va;  ysB[i] = vb;
        ynA = fmaf(va, va, ynA);
        ynB = fmaf(vb, vb, ynB);
    }
    ynA = warpReduceSum(ynA);
    ynB = warpReduceSum(ynB);
    __syncwarp();

    const int base = lane * 5;
    float a0 = kpA[base + 0], a1 = kpA[base + 1], a2 = kpA[base + 2],
          a3 = kpA[base + 3], a4 = kpA[base + 4];
    float b0 = kpB[base + 0], b1 = kpB[base + 1], b2 = kpB[base + 2],
          b3 = kpB[base + 3], b4 = kpB[base + 4];
    const float iA0 = a0, iA1 = a1, iA2 = a2, iA3 = a3;
    const float iB0 = b0, iB1 = b1, iB2 = b2, iB3 = b3;

    float dA0 = 0, dA1 = 0, dA2 = 0, dA3 = 0, dA4 = 0, cA = 0;
    float dB0 = 0, dB1 = 0, dB2 = 0, dB3 = 0, dB4 = 0, cB = 0;
#pragma unroll
    for (int i = 0; i < IDIM; ++i) {
        float va = ysA[i];
        float vb = ysB[i];
        dA0 = fmaf(a0, va, dA0);   dB0 = fmaf(b0, vb, dB0);
        dA1 = fmaf(a1, va, dA1);   dB1 = fmaf(b1, vb, dB1);
        dA2 = fmaf(a2, va, dA2);   dB2 = fmaf(b2, vb, dB2);
        dA3 = fmaf(a3, va, dA3);   dB3 = fmaf(b3, vb, dB3);
        dA4 = fmaf(a4, va, dA4);   dB4 = fmaf(b4, vb, dB4);
        if (i < IDIM - 4) { cA = fmaf(a4, a4, cA); cB = fmaf(b4, b4, cB); }
        a0 = a1; a1 = a2; a2 = a3; a3 = a4;
        b0 = b1; b1 = b2; b2 = b3; b3 = b4;
        a4 = kpA[base + 5 + i];
        b4 = kpB[base + 5 + i];
    }

    // per-pair epilogue (exact R14 math), q=0 -> A, q=1 -> B
    int   bsv[2];
#pragma unroll
    for (int q = 0; q < 2; ++q) {
        const float* kpw = q ? kpB : kpA;
        const float  core = q ? cB : cA;
        float dotv[5];
        if (q) { dotv[0]=dB0; dotv[1]=dB1; dotv[2]=dB2; dotv[3]=dB3; dotv[4]=dB4; }
        else   { dotv[0]=dA0; dotv[1]=dA1; dotv[2]=dA2; dotv[3]=dA3; dotv[4]=dA4; }
        const float i0 = q ? iB0 : iA0, i1 = q ? iB1 : iA1,
                    i2 = q ? iB2 : iA2, i3 = q ? iB3 : iA3;
        const float t0 = kpw[base + 80], t1 = kpw[base + 81],
                    t2 = kpw[base + 82], t3 = kpw[base + 83];
        const float H3 = i3 * i3;
        const float H2 = fmaf(i2, i2, H3);
        const float H1 = fmaf(i1, i1, H2);
        const float H0 = fmaf(i0, i0, H1);
        const float T1 = t0 * t0;
        const float T2 = fmaf(t1, t1, T1);
        const float T3 = fmaf(t2, t2, T2);
        const float T4 = fmaf(t3, t3, T3);

        float n2v[5];
        n2v[0] = H0 + core;
        n2v[1] = (H1 + core) + T1;
        n2v[2] = (H2 + core) + T2;
        n2v[3] = (H3 + core) + T3;
        n2v[4] = core + T4;

        const float yn = sqrtf(q ? ynB : ynA);
        float best = -FLT_MAX;
        int   bidx = 0;
#pragma unroll
        for (int j = 0; j < 5; ++j) {
            int s = base + j;
            if (s < NSHIFT) {
                float den = sqrtf(n2v[j]) * yn;
                float sim = (den > 0.0f) ? (dotv[j] / den) : 0.0f;
                if (sim > best) { best = sim; bidx = s; }
            }
        }
#pragma unroll
        for (int o = 16; o; o >>= 1) {
            float ov = __shfl_xor_sync(0xffffffffu, best, o);
            int   oi = __shfl_xor_sync(0xffffffffu, bidx, o);
            if (ov > best || (ov == best && oi < bidx)) { best = ov; bidx = oi; }
        }
        bsv[q] = bidx;
    }

#pragma unroll
    for (int q = 0; q < 2; ++q) {
        const float* kpw = q ? kpB : kpA;
        const float* ysw = q ? ysB : ysA;
        const int    p   = q ? pB : pA;
        const int    bs  = bsv[q];

        float xa[3], sc[3];
        float m = -FLT_MAX;
#pragma unroll
        for (int t = 0; t < 3; ++t) {
            int i = lane + t * 32;
            if (i < IDIM) {
                xa[t] = kpw[bs + i];
                sc[t] = xa[t] * ysw[i];
                m = fmaxf(m, sc[t]);
            }
        }
        m = warpReduceMax(m);
        float sum = 0.0f, e[3];
#pragma unroll
        for (int t = 0; t < 3; ++t) {
            int i = lane + t * 32;
            if (i < IDIM) { e[t] = expf((sc[t] - m) * 0.1f); sum += e[t]; }
        }
        sum = warpReduceSum(sum);
        const float inv = 1.0f / sum;
#pragma unroll
        for (int t = 0; t < 3; ++t) {
            int i = lane + t * 32;
            if (i < IDIM) {
                float v = xa[t] * (e[t] * inv);
                unsigned short h;
                asm("cvt.rn.f16.f32 %0, %1;" : "=h"(h) : "f"(v));
                xattn_h[(size_t)p * IDIM + i] = h;
            }
        }
    }
}

// ---------------------------------------------------------------------------
// Kernel 2 (UNCHANGED from R14 — validated): fp16 mma.m16n8k16 with
// ldmatrix fragment loads; fp16 A tile copied raw. Block 128x128.
// ---------------------------------------------------------------------------
#define SP2 44   // uint stride per row

__device__ __forceinline__ unsigned f16pack(float v0, float v1) {
    unsigned r;
    asm("cvt.rn.f16x2.f32 %0, %1, %2;" : "=r"(r) : "f"(v1), "f"(v0));
    return r;
}

__device__ __forceinline__ void mma_f16(float d[4],
                                        unsigned a0, unsigned a1,
                                        unsigned a2, unsigned a3,
                                        unsigned b0, unsigned b1) {
    asm("mma.sync.aligned.m16n8k16.row.col.f32.f16.f16.f32 "
        "{%0,%1,%2,%3}, {%4,%5,%6,%7}, {%8,%9}, {%0,%1,%2,%3};"
        : "+f"(d[0]), "+f"(d[1]), "+f"(d[2]), "+f"(d[3])
        : "r"(a0), "r"(a1), "r"(a2), "r"(a3), "r"(b0), "r"(b1));
}

__device__ __forceinline__ void ldsm_x4(unsigned& r0, unsigned& r1,
                                        unsigned& r2, unsigned& r3,
                                        unsigned addr) {
    asm volatile("ldmatrix.sync.aligned.m8n8.x4.shared.b16 {%0,%1,%2,%3}, [%4];"
                 : "=r"(r0), "=r"(r1), "=r"(r2), "=r"(r3) : "r"(addr));
}

__global__ __launch_bounds__(256, 2) void gemm_kernel(
    const unsigned short* __restrict__ Ah, const float* __restrict__ W,
    const float* __restrict__ bias, float* __restrict__ out)
{
    extern __shared__ unsigned smem_u[];
    unsigned* As = smem_u;
    unsigned* Bs = smem_u + 128 * SP2;

    const int bn  = blockIdx.x * 128;
    const int bm  = blockIdx.y * 128;
    const int tid = threadIdx.x;
    const int warp = tid >> 5, lane = tid & 31;
    const int wm = warp >> 2;
    const int wn = warp & 3;
    const int g  = lane >> 2;
    const int t  = lane & 3;

#pragma unroll
    for (int it = 0; it < 5; ++it) {
        int idx = tid + it * 256;
        int row = idx / 10;
        int c4  = (idx % 10) * 4;
        uint4 a = *reinterpret_cast<const uint4*>(
            Ah + (size_t)(bm + row) * IDIM + c4 * 2);
        *reinterpret_cast<uint4*>(&As[row * SP2 + c4]) = a;
    }
#pragma unroll
    for (int it = 0; it < 10; ++it) {
        int idx = tid + it * 256;
        int row = idx / 20;
        int k4  = (idx % 20) * 4;
        int c   = k4 >> 1;
        float4 b = *reinterpret_cast<const float4*>(W + (size_t)(bn + row) * IDIM + k4);
        *reinterpret_cast<uint2*>(&Bs[row * SP2 + c]) =
            make_uint2(f16pack(b.x, b.y), f16pack(b.z, b.w));
    }
    __syncthreads();

    unsigned a_addr[4];
#pragma unroll
    for (int mt = 0; mt < 4; ++mt) {
        int row = wm * 64 + mt * 16 + (lane & 7) + ((lane >> 3) & 1) * 8;
        int uoff = row * SP2 + (lane >> 4) * 4;
        a_addr[mt] = (unsigned)__cvta_generic_to_shared(As + uoff);
    }
    unsigned b_addr[2];
#pragma unroll
    for (int j = 0; j < 2; ++j) {
        int row = wn * 32 + j * 16 + (lane & 7) + ((lane >> 4) & 1) * 8;
        int uoff = row * SP2 + ((lane >> 3) & 1) * 4;
        b_addr[j] = (unsigned)__cvta_generic_to_shared(Bs + uoff);
    }

    float d[4][4][4];
#pragma unroll
    for (int mt = 0; mt < 4; ++mt)
#pragma unroll
        for (int nt = 0; nt < 4; ++nt)
#pragma unroll
            for (int r = 0; r < 4; ++r) d[mt][nt][r] = 0.0f;

#pragma unroll
    for (int kc = 0; kc < 5; ++kc) {
        const unsigned koff = kc * 32;

        unsigned b0[4], b1[4];
        ldsm_x4(b0[0], b1[0], b0[1], b1[1], b_addr[0] + koff);
        ldsm_x4(b0[2], b1[2], b0[3], b1[3], b_addr[1] + koff);

#pragma unroll
        for (int mt = 0; mt < 4; ++mt) {
            unsigned a0, a1, a2, a3;
            ldsm_x4(a0, a1, a2, a3, a_addr[mt] + koff);
#pragma unroll
            for (int nt = 0; nt < 4; ++nt)
                mma_f16(d[mt][nt], a0, a1, a2, a3, b0[nt], b1[nt]);
        }
    }

#pragma unroll
    for (int mt = 0; mt < 4; ++mt) {
#pragma unroll
        for (int nt = 0; nt < 4; ++nt) {
            int row = bm + wm * 64 + mt * 16 + g;
            int col = bn + wn * 32 + nt * 8 + 2 * t;
            float b0 = __ldg(bias + col), b1 = __ldg(bias + col + 1);
            float2 o0 = make_float2(d[mt][nt][0] + b0, d[mt][nt][1] + b1);
            float2 o1 = make_float2(d[mt][nt][2] + b0, d[mt][nt][3] + b1);
            *reinterpret_cast<float2*>(out + (size_t)row * HDIM + col) = o0;
            *reinterpret_cast<float2*>(out + (size_t)(row + 8) * HDIM + col) = o1;
        }
    }
}

extern "C" void kernel_launch(void* const* d_in, const int* in_sizes, int n_in,
                              void* d_out, int out_size)
{
    const float* x    = (const float*)d_in[0];
    const float* y    = (const float*)d_in[1];
    const float* fc1w = (const float*)d_in[2];
    const float* fc1b = (const float*)d_in[3];
    float* out = (float*)d_out;

    unsigned short* xattn_h = nullptr;
    cudaGetSymbolAddress((void**)&xattn_h, g_xattn_h);

    attn_kernel<<<BT / PAIRS_PER_BLK, 256>>>(x, y, xattn_h);

    const int smem_bytes = 2 * 128 * SP2 * (int)sizeof(unsigned);  // 45056
    cudaFuncSetAttribute(gemm_kernel,
                         cudaFuncAttributeMaxDynamicSharedMemorySize, smem_bytes);
    gemm_kernel<<<dim3(HDIM / 128, BT / 128), 256, smem_bytes>>>(
        xattn_h, fc1w, fc1b, out);
}